// round 7
// baseline (speedup 1.0000x reference)
#include <cuda_runtime.h>
#include <stdint.h>

// Problem constants
#define NSAMP 1000000u
#define KMIX  64
#define DDIM  16
#define LSTRIDE 260          // padded words per L matrix (256 + 4)

// ---------------------------------------------------------------------------
// Threefry-2x32, key = (0, 42), partitionable counter (0, i), combine o0^o1.
// Adds are written as x*one + c with runtime-opaque one==1 so ptxas emits
// IMAD (FMA pipe) instead of IADD3 (ALU pipe) — rebalances the two pipes.
// ---------------------------------------------------------------------------
__device__ __forceinline__ uint32_t tf_bits(uint32_t clo, uint32_t one) {
    const uint32_t ks1 = 42u;
    const uint32_t ks2 = 0x1BD11BDAu ^ 42u;

    uint32_t x1 = clo + ks1;
    uint32_t x0 = x1;                       // round-1 specialized (x0 starts 0)
    x1 = __funnelshift_l(x1, x1, 13) ^ x0;

#define TFR(r) { x0 = x1 * one + x0; x1 = __funnelshift_l(x1, x1, (r)) ^ x0; }
    TFR(15) TFR(26) TFR(6)
    x0 = x0 * one + ks1;  x1 = x1 * one + (ks2 + 1u);
    TFR(17) TFR(29) TFR(16) TFR(24)
    x0 = x0 * one + ks2;  x1 = x1 * one + 2u;            // ks0 = 0
    TFR(13) TFR(15) TFR(26) TFR(6)
    /* x0 += ks0 (=0): skip */
    x1 = x1 * one + (ks1 + 3u);
    TFR(17) TFR(29) TFR(16) TFR(24)
    x0 = x0 * one + ks1;  x1 = x1 * one + (ks2 + 4u);
    TFR(13) TFR(15) TFR(26) TFR(6)
    x0 = x0 * one + ks2;  x1 = x1 * one + 5u;            // ks0 = 0
#undef TFR

    return x0 ^ x1;
}

// ---------------------------------------------------------------------------
// Fused kernel: block-local logits -> categorical sample -> matvec.
// Ls + means staged in shared (71 KB) to kill z-scattered L1 gathers.
// Screen: argmin_k (-log2(u_k)) * (ln2/p_k), packed-int top-2 tracking;
// exact reference-formula rescan when top-2 margin < 1e-3(1+m1).
// ---------------------------------------------------------------------------
__global__ __launch_bounds__(256) void fused_kernel(
    const float* __restrict__ pi,
    const float* __restrict__ x,
    const float* __restrict__ means,
    const float* __restrict__ Ls,
    float* __restrict__ y)
{
    extern __shared__ float sm[];
    float* sL   = sm;                        // 64 * 260 = 16640 words
    float* sMu  = sm + KMIX * LSTRIDE;       // 1024 words
    float* sW2n = sMu + KMIX * DDIM;         // 64
    float* sLg  = sW2n + KMIX;               // 64
    __shared__ float sSum;

    int tid = threadIdx.x;

    // Stage Ls into padded shared (coalesced float4 loads).
    #pragma unroll
    for (int i = tid; i < KMIX * 64; i += 256) {
        int k = i >> 6, r = i & 63;
        float4 v = __ldg((const float4*)Ls + i);
        *(float4*)(sL + k * LSTRIDE + r * 4) = v;
    }
    {   // means: 256 float4s, one per thread
        float4 v = __ldg((const float4*)means + tid);
        *(float4*)(sMu + tid * 4) = v;
    }
    if (tid == 0) {                          // serial sum order: bit-identical
        float s = 0.0f;                      // to all verified runs
        for (int k = 0; k < KMIX; k++) s += pi[k];
        sSum = s;
    }
    __syncthreads();
    if (tid < KMIX) {
        float ssum = sSum;
        sLg[tid]  = logf(pi[tid] / ssum);
        sW2n[tid] = -0.6931471805599453f * (ssum / pi[tid]);  // -ln2/p_k
    }
    __syncthreads();

    uint32_t one = (sSum != 0.0f) ? 1u : 0u;   // runtime-opaque 1

    unsigned n  = blockIdx.x * 256u + threadIdx.x;
    unsigned nc = n < NSAMP ? n : (NSAMP - 1u);
    uint32_t base = nc * 64u;

    // ---- categorical sample (screen) ----
    uint32_t im1 = 0xFFFFFFFFu, im2 = 0xFFFFFFFFu;

    #pragma unroll 8
    for (int k = 0; k < KMIX; k++) {
        uint32_t bits = tf_bits(base + (uint32_t)k, one);
        uint32_t fb;
        // fb = (bits >> 9) + 0x3F800000  in one IMAD.HI (FMA pipe)
        asm("mad.hi.u32 %0, %1, %2, %3;"
            : "=r"(fb) : "r"(bits), "r"(0x00800000u), "r"(0x3F800000u));
        float u = __uint_as_float(fb) - 1.0f;           // in [0,1)
        float m = __log2f(u) * sW2n[k];                 // = -log2(u)*ln2/p_k >= 0
        uint32_t im = (__float_as_uint(m) & 0xFFFFFFC0u) | (uint32_t)k;
        uint32_t mx = im1 > im ? im1 : im;              // IMNMX umax
        im2 = im2 < mx ? im2 : mx;                      // IMNMX umin
        im1 = im1 < im ? im1 : im;                      // IMNMX umin
    }

    int z = (int)(im1 & 63u);
    float m1 = __uint_as_float(im1 & 0xFFFFFFC0u);
    float m2 = __uint_as_float(im2 & 0xFFFFFFC0u);

    if (m2 - m1 < 1e-3f + 1e-3f * m1) {
        // Exact reference-formula rescan (verified bit-exact path).
        float best = -__int_as_float(0x7F800000);
        int zi = 0;
        for (int k = 0; k < KMIX; k++) {
            uint32_t bits = tf_bits(base + (uint32_t)k, one);
            float f  = __uint_as_float(0x3F800000u | (bits >> 9)) - 1.0f;
            float uu = fmaxf(f, 1.17549435e-38f);
            float v  = -logf(-logf(uu)) + sLg[k];
            if (v > best) { best = v; zi = k; }
        }
        z = zi;
    }

    // ---- matvec from shared: y[n] = x[n]^T @ L[z] + mu[z] ----
    const float4* xg = (const float4*)x + nc * 4;
    float4 xa = __ldg(xg + 0);
    float4 xb = __ldg(xg + 1);
    float4 xc = __ldg(xg + 2);
    float4 xd = __ldg(xg + 3);
    float xr[16] = { xa.x, xa.y, xa.z, xa.w,
                     xb.x, xb.y, xb.z, xb.w,
                     xc.x, xc.y, xc.z, xc.w,
                     xd.x, xd.y, xd.z, xd.w };

    const float* Lb = sL + z * LSTRIDE;
    const float* Mb = sMu + z * DDIM;
    float4 acc0 = *(const float4*)(Mb + 0);
    float4 acc1 = *(const float4*)(Mb + 4);
    float4 acc2 = *(const float4*)(Mb + 8);
    float4 acc3 = *(const float4*)(Mb + 12);

    #pragma unroll
    for (int d = 0; d < DDIM; d++) {
        float xs = xr[d];
        float4 l0 = *(const float4*)(Lb + d * 16 + 0);
        float4 l1 = *(const float4*)(Lb + d * 16 + 4);
        float4 l2 = *(const float4*)(Lb + d * 16 + 8);
        float4 l3 = *(const float4*)(Lb + d * 16 + 12);
        acc0.x = fmaf(xs, l0.x, acc0.x); acc0.y = fmaf(xs, l0.y, acc0.y);
        acc0.z = fmaf(xs, l0.z, acc0.z); acc0.w = fmaf(xs, l0.w, acc0.w);
        acc1.x = fmaf(xs, l1.x, acc1.x); acc1.y = fmaf(xs, l1.y, acc1.y);
        acc1.z = fmaf(xs, l1.z, acc1.z); acc1.w = fmaf(xs, l1.w, acc1.w);
        acc2.x = fmaf(xs, l2.x, acc2.x); acc2.y = fmaf(xs, l2.y, acc2.y);
        acc2.z = fmaf(xs, l2.z, acc2.z); acc2.w = fmaf(xs, l2.w, acc2.w);
        acc3.x = fmaf(xs, l3.x, acc3.x); acc3.y = fmaf(xs, l3.y, acc3.y);
        acc3.z = fmaf(xs, l3.z, acc3.z); acc3.w = fmaf(xs, l3.w, acc3.w);
    }

    if (n < NSAMP) {
        float4* y4 = (float4*)y + n * 4;
        y4[0] = acc0; y4[1] = acc1; y4[2] = acc2; y4[3] = acc3;
    }
}

// ---------------------------------------------------------------------------
extern "C" void kernel_launch(void* const* d_in, const int* in_sizes, int n_in,
                              void* d_out, int out_size) {
    const float* x     = (const float*)d_in[0];   // (N, D)
    const float* pi    = (const float*)d_in[1];   // (K,)
    const float* means = (const float*)d_in[2];   // (K, D)
    const float* Ls    = (const float*)d_in[3];   // (K, D, D)
    float* y           = (float*)d_out;           // (N, D)

    const int smem_bytes = (KMIX * LSTRIDE + KMIX * DDIM + KMIX + KMIX) * 4;
    cudaFuncSetAttribute(fused_kernel,
                         cudaFuncAttributeMaxDynamicSharedMemorySize, smem_bytes);
    fused_kernel<<<(NSAMP + 255) / 256, 256, smem_bytes>>>(pi, x, means, Ls, y);
}

// round 8
// speedup vs baseline: 1.2426x; 1.2426x over previous
#include <cuda_runtime.h>
#include <stdint.h>

// Problem constants
#define NSAMP 1000000u
#define KMIX  64
#define DDIM  16
#define LSTRIDE 260          // padded words per L matrix (256 + 4)

// Opaque 1 — a global load ptxas cannot constant-fold, so mad.lo.u32 by this
// value MUST stay an IMAD (FMA pipe), rebalancing work off the ALU pipe.
__device__ uint32_t g_one = 1u;

// ---------------------------------------------------------------------------
// Threefry-2x32, key = (0, 42), partitionable counter (0, i), combine o0^o1.
// Round adds are explicit IMADs (x0 = x1*one + x0) on the FMA pipe.
// Keyschedule adds stay plain IADD3 (ptxas fuses them 3-input).
// ---------------------------------------------------------------------------
__device__ __forceinline__ uint32_t tf_bits(uint32_t clo, uint32_t one) {
    const uint32_t ks1 = 42u;
    const uint32_t ks2 = 0x1BD11BDAu ^ 42u;

    uint32_t x1 = clo + ks1;
    uint32_t x0 = x1;                       // round-1 specialized (x0 starts 0)
    x1 = __funnelshift_l(x1, x1, 13) ^ x0;

#define TFR(r) { asm("mad.lo.u32 %0, %1, %2, %0;" : "+r"(x0) : "r"(x1), "r"(one)); \
                 x1 = __funnelshift_l(x1, x1, (r)) ^ x0; }
    TFR(15) TFR(26) TFR(6)
    x0 += ks1;  x1 += ks2 + 1u;
    TFR(17) TFR(29) TFR(16) TFR(24)
    x0 += ks2;  x1 += 2u;                   // ks0 = 0
    TFR(13) TFR(15) TFR(26) TFR(6)
    /* x0 += ks0 (=0): skip */
    x1 += ks1 + 3u;
    TFR(17) TFR(29) TFR(16) TFR(24)
    x0 += ks1;  x1 += ks2 + 4u;
    TFR(13) TFR(15) TFR(26) TFR(6)
    x0 += ks2;  x1 += 5u;                   // ks0 = 0
#undef TFR

    return x0 ^ x1;
}

// ---------------------------------------------------------------------------
// Fused kernel: block-local logits -> categorical sample -> matvec.
// Ls + means staged in shared (71 KB): matvec gathers hit LDS, not L1tex.
// Screen: argmin_k log2(u_k) * (-ln2/p_k)  (monotone-equiv to ref argmax),
// float top-2 tracking; exact reference-formula rescan when the top-2
// margin < 1e-3 + 1e-3*m1 (>=130x over worst-case MUFU.LG2 error).
// ---------------------------------------------------------------------------
__global__ __launch_bounds__(256) void fused_kernel(
    const float* __restrict__ pi,
    const float* __restrict__ x,
    const float* __restrict__ means,
    const float* __restrict__ Ls,
    float* __restrict__ y)
{
    extern __shared__ float sm[];
    float* sL   = sm;                        // 64 * 260 = 16640 words
    float* sMu  = sm + KMIX * LSTRIDE;       // 1024 words
    float* sW2n = sMu + KMIX * DDIM;         // 64
    float* sLg  = sW2n + KMIX;               // 64
    __shared__ float sSum;

    int tid = threadIdx.x;

    // Stage Ls into padded shared (coalesced float4 loads).
    #pragma unroll
    for (int i = tid; i < KMIX * 64; i += 256) {
        int k = i >> 6, r = i & 63;
        float4 v = __ldg((const float4*)Ls + i);
        *(float4*)(sL + k * LSTRIDE + r * 4) = v;
    }
    {   // means: 256 float4s, one per thread
        float4 v = __ldg((const float4*)means + tid);
        *(float4*)(sMu + tid * 4) = v;
    }
    if (tid == 0) {                          // serial sum order: bit-identical
        float s = 0.0f;                      // to all verified runs
        for (int k = 0; k < KMIX; k++) s += pi[k];
        sSum = s;
    }
    __syncthreads();
    if (tid < KMIX) {
        float ssum = sSum;
        sLg[tid]  = logf(pi[tid] / ssum);
        sW2n[tid] = -0.6931471805599453f * (ssum / pi[tid]);  // -ln2/p_k
    }
    __syncthreads();

    uint32_t one = g_one;                    // opaque 1 (global load)

    unsigned n  = blockIdx.x * 256u + threadIdx.x;
    unsigned nc = n < NSAMP ? n : (NSAMP - 1u);
    uint32_t base = nc * 64u;

    // ---- categorical sample (screen, R6-style float top-2 tracking) ----
    const float INF = __int_as_float(0x7F800000);
    float m1 = INF, m2 = INF;
    int i1 = 0;

    #pragma unroll 8
    for (int k = 0; k < KMIX; k++) {
        uint32_t bits = tf_bits(base + (uint32_t)k, one);
        uint32_t fb;
        // fb = (bits >> 9) + 0x3F800000 in one IMAD.HI (FMA pipe)
        asm("mad.hi.u32 %0, %1, %2, %3;"
            : "=r"(fb) : "r"(bits), "r"(0x00800000u), "r"(0x3F800000u));
        float u = __uint_as_float(fb) - 1.0f;           // in [0,1)
        float m = __log2f(u) * sW2n[k];                 // >= 0 (u=0 -> +inf, never min)
        if (m < m1) { m2 = m1; m1 = m; i1 = k; }
        else        { m2 = fminf(m2, m); }
    }

    int z = i1;
    if (m2 - m1 < 1e-3f + 1e-3f * m1) {
        // Exact reference-formula rescan (verified bit-exact path).
        float best = -INF;
        int zi = 0;
        for (int k = 0; k < KMIX; k++) {
            uint32_t bits = tf_bits(base + (uint32_t)k, one);
            float f  = __uint_as_float(0x3F800000u | (bits >> 9)) - 1.0f;
            float uu = fmaxf(f, 1.17549435e-38f);
            float v  = -logf(-logf(uu)) + sLg[k];
            if (v > best) { best = v; zi = k; }
        }
        z = zi;
    }

    // ---- matvec from shared: y[n] = x[n]^T @ L[z] + mu[z] ----
    const float4* xg = (const float4*)x + nc * 4;
    float4 xa = __ldg(xg + 0);
    float4 xb = __ldg(xg + 1);
    float4 xc = __ldg(xg + 2);
    float4 xd = __ldg(xg + 3);
    float xr[16] = { xa.x, xa.y, xa.z, xa.w,
                     xb.x, xb.y, xb.z, xb.w,
                     xc.x, xc.y, xc.z, xc.w,
                     xd.x, xd.y, xd.z, xd.w };

    const float* Lb = sL + z * LSTRIDE;
    const float* Mb = sMu + z * DDIM;
    float4 acc0 = *(const float4*)(Mb + 0);
    float4 acc1 = *(const float4*)(Mb + 4);
    float4 acc2 = *(const float4*)(Mb + 8);
    float4 acc3 = *(const float4*)(Mb + 12);

    #pragma unroll
    for (int d = 0; d < DDIM; d++) {
        float xs = xr[d];
        float4 l0 = *(const float4*)(Lb + d * 16 + 0);
        float4 l1 = *(const float4*)(Lb + d * 16 + 4);
        float4 l2 = *(const float4*)(Lb + d * 16 + 8);
        float4 l3 = *(const float4*)(Lb + d * 16 + 12);
        acc0.x = fmaf(xs, l0.x, acc0.x); acc0.y = fmaf(xs, l0.y, acc0.y);
        acc0.z = fmaf(xs, l0.z, acc0.z); acc0.w = fmaf(xs, l0.w, acc0.w);
        acc1.x = fmaf(xs, l1.x, acc1.x); acc1.y = fmaf(xs, l1.y, acc1.y);
        acc1.z = fmaf(xs, l1.z, acc1.z); acc1.w = fmaf(xs, l1.w, acc1.w);
        acc2.x = fmaf(xs, l2.x, acc2.x); acc2.y = fmaf(xs, l2.y, acc2.y);
        acc2.z = fmaf(xs, l2.z, acc2.z); acc2.w = fmaf(xs, l2.w, acc2.w);
        acc3.x = fmaf(xs, l3.x, acc3.x); acc3.y = fmaf(xs, l3.y, acc3.y);
        acc3.z = fmaf(xs, l3.z, acc3.z); acc3.w = fmaf(xs, l3.w, acc3.w);
    }

    if (n < NSAMP) {
        float4* y4 = (float4*)y + n * 4;
        y4[0] = acc0; y4[1] = acc1; y4[2] = acc2; y4[3] = acc3;
    }
}

// ---------------------------------------------------------------------------
extern "C" void kernel_launch(void* const* d_in, const int* in_sizes, int n_in,
                              void* d_out, int out_size) {
    const float* x     = (const float*)d_in[0];   // (N, D)
    const float* pi    = (const float*)d_in[1];   // (K,)
    const float* means = (const float*)d_in[2];   // (K, D)
    const float* Ls    = (const float*)d_in[3];   // (K, D, D)
    float* y           = (float*)d_out;           // (N, D)

    const int smem_bytes = (KMIX * LSTRIDE + KMIX * DDIM + KMIX + KMIX) * 4;
    cudaFuncSetAttribute(fused_kernel,
                         cudaFuncAttributeMaxDynamicSharedMemorySize, smem_bytes);
    fused_kernel<<<(NSAMP + 255u) / 256u, 256, smem_bytes>>>(pi, x, means, Ls, y);
}